// round 7
// baseline (speedup 1.0000x reference)
#include <cuda_runtime.h>
#include <cuda_bf16.h>
#include <cstdint>

// ---------------- model dims ----------------
#define B_    8
#define L_    512
#define D_IN  128
#define D_MODEL 512
#define N_LAYERS 2
#define D_STATE 16
#define D_CONV  4
#define D_INNER 1024
#define DT_RANK 32
#define ML (B_ * L_)
#define XKS 4                      // split-K factor for x_proj

// ---------------- scratch ----------------
__device__ float g_ha[ML * D_MODEL];
__device__ float g_xz[ML * 2 * D_INNER];
__device__ float g_xc[ML * D_INNER];
__device__ float g_xdbl[ML * 64];
__device__ float g_xpart[XKS * ML * 64];
__device__ float g_dt[ML * D_INNER];
__device__ float g_hpart[B_ * 8 * D_MODEL];
__device__ float g_hm[B_ * D_MODEL];

// bf16 hi/lo planes
__device__ __align__(16) __nv_bfloat16 g_xh[ML * D_IN];
__device__ __align__(16) __nv_bfloat16 g_xl[ML * D_IN];
__device__ __align__(16) __nv_bfloat16 g_piwh[D_MODEL * D_IN];
__device__ __align__(16) __nv_bfloat16 g_piwl[D_MODEL * D_IN];
__device__ __align__(16) __nv_bfloat16 g_inwh[N_LAYERS * 2 * D_INNER * D_MODEL];
__device__ __align__(16) __nv_bfloat16 g_inwl[N_LAYERS * 2 * D_INNER * D_MODEL];
__device__ __align__(16) __nv_bfloat16 g_outwh[N_LAYERS * D_MODEL * D_INNER];
__device__ __align__(16) __nv_bfloat16 g_outwl[N_LAYERS * D_MODEL * D_INNER];
// zero-padded weight planes (pad regions never written -> stay zero)
__device__ __align__(16) __nv_bfloat16 g_xpwh[N_LAYERS * 128 * D_INNER];
__device__ __align__(16) __nv_bfloat16 g_xpwl[N_LAYERS * 128 * D_INNER];
__device__ __align__(16) __nv_bfloat16 g_dtwh[N_LAYERS * D_INNER * 64];
__device__ __align__(16) __nv_bfloat16 g_dtwl[N_LAYERS * D_INNER * 64];
// activation planes
__device__ __align__(16) __nv_bfloat16 g_hh[ML * D_MODEL];
__device__ __align__(16) __nv_bfloat16 g_hl[ML * D_MODEL];
__device__ __align__(16) __nv_bfloat16 g_xch[ML * D_INNER];
__device__ __align__(16) __nv_bfloat16 g_xcl[ML * D_INNER];
__device__ __align__(16) __nv_bfloat16 g_xdblh[ML * 64];
__device__ __align__(16) __nv_bfloat16 g_xdbll[ML * 64];
__device__ __align__(16) __nv_bfloat16 g_yh[ML * D_INNER];
__device__ __align__(16) __nv_bfloat16 g_yl[ML * D_INNER];

__device__ __forceinline__ float act_silu(float v) { return v / (1.f + __expf(-v)); }
__device__ __forceinline__ float act_softplus(float v) { return (v > 20.f) ? v : log1pf(__expf(v)); }

// =====================================================================
// PTX helpers
// =====================================================================
__device__ __forceinline__ void ldsm_x4(uint32_t* r, uint32_t addr) {
    asm volatile("ldmatrix.sync.aligned.m8n8.x4.shared.b16 {%0,%1,%2,%3}, [%4];"
                 : "=r"(r[0]), "=r"(r[1]), "=r"(r[2]), "=r"(r[3]) : "r"(addr));
}
__device__ __forceinline__ void mma16816(float* c, const uint32_t* a, const uint32_t* b) {
    asm volatile(
        "mma.sync.aligned.m16n8k16.row.col.f32.bf16.bf16.f32 "
        "{%0,%1,%2,%3}, {%4,%5,%6,%7}, {%8,%9}, {%0,%1,%2,%3};"
        : "+f"(c[0]), "+f"(c[1]), "+f"(c[2]), "+f"(c[3])
        : "r"(a[0]), "r"(a[1]), "r"(a[2]), "r"(a[3]), "r"(b[0]), "r"(b[1]));
}
__device__ __forceinline__ void cp16(uint32_t dst, const void* src) {
    asm volatile("cp.async.cg.shared.global [%0], [%1], 16;" :: "r"(dst), "l"(src));
}
#define CP_COMMIT() asm volatile("cp.async.commit_group;" ::: "memory")
#define CP_WAIT(n)  asm volatile("cp.async.wait_group %0;" :: "n"(n) : "memory")

__device__ __forceinline__ uint32_t bf2_bits(__nv_bfloat162 v) {
    return *reinterpret_cast<const uint32_t*>(&v);
}

// ---------------- fp32 -> bf16 hi/lo split (two tensors per launch) ----------------
__global__ void cvt_split2(const float* __restrict__ s0,
                           __nv_bfloat16* __restrict__ h0, __nv_bfloat16* __restrict__ l0, int n0,
                           const float* __restrict__ s1,
                           __nv_bfloat16* __restrict__ h1, __nv_bfloat16* __restrict__ l1, int n1)
{
    int i = blockIdx.x * blockDim.x + threadIdx.x;
    const float* src; __nv_bfloat16 *h, *l;
    if (i < n0) { src = s0; h = h0; l = l0; }
    else {
        i -= n0;
        if (i >= n1) return;
        src = s1; h = h1; l = l1;
    }
    float4 v = reinterpret_cast<const float4*>(src)[i];
    __nv_bfloat162 hh0 = __floats2bfloat162_rn(v.x, v.y);
    __nv_bfloat162 hh1 = __floats2bfloat162_rn(v.z, v.w);
    __nv_bfloat162 ll0 = __floats2bfloat162_rn(v.x - __bfloat162float(hh0.x),
                                               v.y - __bfloat162float(hh0.y));
    __nv_bfloat162 ll1 = __floats2bfloat162_rn(v.z - __bfloat162float(hh1.x),
                                               v.w - __bfloat162float(hh1.y));
    reinterpret_cast<uint2*>(h)[i] = make_uint2(bf2_bits(hh0), bf2_bits(hh1));
    reinterpret_cast<uint2*>(l)[i] = make_uint2(bf2_bits(ll0), bf2_bits(ll1));
}

// dt_proj_w (NL,1024,32) -> padded planes (NL,1024,64); cols 32..63 stay zero
__global__ void cvt_dtw(const float* __restrict__ src,
                        __nv_bfloat16* __restrict__ h, __nv_bfloat16* __restrict__ l)
{
    int i = blockIdx.x * blockDim.x + threadIdx.x;      // quads
    if (i >= N_LAYERS * D_INNER * 8) return;
    int row = i >> 3, q = i & 7;
    float4 v = *reinterpret_cast<const float4*>(src + row * 32 + q * 4);
    __nv_bfloat162 hh0 = __floats2bfloat162_rn(v.x, v.y);
    __nv_bfloat162 hh1 = __floats2bfloat162_rn(v.z, v.w);
    __nv_bfloat162 ll0 = __floats2bfloat162_rn(v.x - __bfloat162float(hh0.x),
                                               v.y - __bfloat162float(hh0.y));
    __nv_bfloat162 ll1 = __floats2bfloat162_rn(v.z - __bfloat162float(hh1.x),
                                               v.w - __bfloat162float(hh1.y));
    *reinterpret_cast<uint2*>(h + row * 64 + q * 4) = make_uint2(bf2_bits(hh0), bf2_bits(hh1));
    *reinterpret_cast<uint2*>(l + row * 64 + q * 4) = make_uint2(bf2_bits(ll0), bf2_bits(ll1));
}

// =====================================================================
// Tensor-core GEMM: 512 threads, 16 warps (4x4), warp tile 32x32,
// CTA 128x128, K-chunk 64, cp.async double buffer (2 x 64KB).
// fp32 = bf16 hi/lo split, 3 MMAs. Optional split-K via blockIdx.z.
// =====================================================================
#define MMA_SMEM_BYTES 131072

__global__ __launch_bounds__(512, 1) void gemm_mma(
    const __nv_bfloat16* __restrict__ Ah, const __nv_bfloat16* __restrict__ Al, int lda,
    const __nv_bfloat16* __restrict__ Wh, const __nv_bfloat16* __restrict__ Wl, int ldw,
    const float* __restrict__ bias, float* __restrict__ C,
    __nv_bfloat16* __restrict__ Ch, __nv_bfloat16* __restrict__ Cl,
    int ldc, int Nstore, int K, int act, size_t zstride)
{
    extern __shared__ char smem[];
    const uint32_t sbase = (uint32_t)__cvta_generic_to_shared(smem);
    const int tid = threadIdx.x;
    const int lane = tid & 31;
    const int wid = tid >> 5;          // 0..15
    const int wm = wid >> 2;           // 0..3 (32-row band)
    const int wn = wid & 3;            // 0..3 (32-col band)
    const int bm = blockIdx.y * 128;
    const int bn = blockIdx.x * 128;
    {
        const int z = blockIdx.z;
        Ah += (size_t)z * K; Al += (size_t)z * K;
        Wh += (size_t)z * K; Wl += (size_t)z * K;
        C  += (size_t)z * zstride;
    }

    // fill coords: 512 thr x 8 cp16 = 64KB/chunk
    const int rf = tid >> 3;           // 0..63
    const int sf = tid & 7;
    const uint32_t sw0 = (uint32_t)(rf * 128 + sf * 16) ^ (((uint32_t)rf & 7u) << 4);

    auto fill = [&](int buf, int k0) {
        const uint32_t bb = sbase + (uint32_t)buf * 65536;
        #pragma unroll
        for (int pl = 0; pl < 4; pl++) {
            const __nv_bfloat16* base = (pl == 0) ? Ah : (pl == 1) ? Al : (pl == 2) ? Wh : Wl;
            const int ld = (pl < 2) ? lda : ldw;
            const int rb = (pl < 2) ? bm : bn;
            #pragma unroll
            for (int hf = 0; hf < 2; hf++) {
                const int row = rf + hf * 64;
                cp16(bb + (uint32_t)pl * 16384 + sw0 + (uint32_t)hf * 8192,
                     base + (size_t)(rb + row) * ld + k0 + sf * 8);
            }
        }
    };

    // fragment lane addressing (SW128: xor = (row&7)<<4)
    const int l7 = lane & 7;
    const uint32_t xorv = (uint32_t)l7 << 4;
    const int a_row = wm * 32 + l7 + ((lane >> 3) & 1) * 8;
    const uint32_t a_kb = (uint32_t)((lane >> 4) & 1) * 16;
    const int b_row = wn * 32 + ((lane >> 4) & 1) * 8 + l7;
    const uint32_t b_kb = (uint32_t)((lane >> 3) & 1) * 16;

    float acc[2][4][4];
    #pragma unroll
    for (int i = 0; i < 2; i++)
        #pragma unroll
        for (int j = 0; j < 4; j++)
            #pragma unroll
            for (int r = 0; r < 4; r++) acc[i][j][r] = 0.f;

    const int nt = K / 64;

    fill(0, 0);
    CP_COMMIT();

    for (int t = 0; t < nt; t++) {
        const int buf = t & 1;
        if (t + 1 < nt) {
            fill(buf ^ 1, (t + 1) * 64);
            CP_COMMIT();
            CP_WAIT(1);
        } else {
            CP_WAIT(0);
        }
        __syncthreads();

        const uint32_t bb = sbase + (uint32_t)buf * 65536;
        #pragma unroll
        for (int kk = 0; kk < 4; kk++) {
            const uint32_t koff_a = ((uint32_t)(kk * 32) + a_kb) ^ xorv;
            const uint32_t koff_b = ((uint32_t)(kk * 32) + b_kb) ^ xorv;
            uint32_t ah[2][4], al[2][4], bh[2][4], bl[2][4];
            #pragma unroll
            for (int i = 0; i < 2; i++) {
                uint32_t ad = bb + (uint32_t)((a_row + i * 16) * 128) + koff_a;
                ldsm_x4(ah[i], ad);
                ldsm_x4(al[i], ad + 16384);
            }
            #pragma unroll
            for (int jj = 0; jj < 2; jj++) {
                uint32_t bd = bb + 32768 + (uint32_t)((b_row + jj * 16) * 128) + koff_b;
                ldsm_x4(bh[jj], bd);
                ldsm_x4(bl[jj], bd + 16384);
            }
            // term-major: 8 independent MMAs between accumulator reuse
            #pragma unroll
            for (int i = 0; i < 2; i++)
                #pragma unroll
                for (int j = 0; j < 4; j++)
                    mma16816(acc[i][j], ah[i], &bh[j >> 1][(j & 1) * 2]);
            #pragma unroll
            for (int i = 0; i < 2; i++)
                #pragma unroll
                for (int j = 0; j < 4; j++)
                    mma16816(acc[i][j], ah[i], &bl[j >> 1][(j & 1) * 2]);
            #pragma unroll
            for (int i = 0; i < 2; i++)
                #pragma unroll
                for (int j = 0; j < 4; j++)
                    mma16816(acc[i][j], al[i], &bh[j >> 1][(j & 1) * 2]);
        }
        __syncthreads();
    }

    // ---- epilogue
    const int g = lane >> 2;
    const int t4 = lane & 3;
    #pragma unroll
    for (int i = 0; i < 2; i++) {
        const int r0 = bm + wm * 32 + i * 16 + g;
        const int r1 = r0 + 8;
        #pragma unroll
        for (int j = 0; j < 4; j++) {
            const int col = bn + wn * 32 + j * 8 + t4 * 2;
            if (col >= Nstore) continue;
            const float b0 = bias ? __ldg(&bias[col]) : 0.f;
            const float b1 = bias ? __ldg(&bias[col + 1]) : 0.f;
            float2 v0 = make_float2(acc[i][j][0] + b0, acc[i][j][1] + b1);
            float2 v1 = make_float2(acc[i][j][2] + b0, acc[i][j][3] + b1);
            if (act == 1) {
                v0.x = act_softplus(v0.x); v0.y = act_softplus(v0.y);
                v1.x = act_softplus(v1.x); v1.y = act_softplus(v1.y);
            }
            if (C) {
                *reinterpret_cast<float2*>(&C[(size_t)r0 * ldc + col]) = v0;
                *reinterpret_cast<float2*>(&C[(size_t)r1 * ldc + col]) = v1;
            }
            if (Ch) {
                __nv_bfloat162 h0 = __floats2bfloat162_rn(v0.x, v0.y);
                __nv_bfloat162 h1 = __floats2bfloat162_rn(v1.x, v1.y);
                __nv_bfloat162 l0 = __floats2bfloat162_rn(v0.x - __bfloat162float(h0.x),
                                                          v0.y - __bfloat162float(h0.y));
                __nv_bfloat162 l1 = __floats2bfloat162_rn(v1.x - __bfloat162float(h1.x),
                                                          v1.y - __bfloat162float(h1.y));
                *reinterpret_cast<uint32_t*>(&Ch[(size_t)r0 * ldc + col]) = bf2_bits(h0);
                *reinterpret_cast<uint32_t*>(&Ch[(size_t)r1 * ldc + col]) = bf2_bits(h1);
                *reinterpret_cast<uint32_t*>(&Cl[(size_t)r0 * ldc + col]) = bf2_bits(l0);
                *reinterpret_cast<uint32_t*>(&Cl[(size_t)r1 * ldc + col]) = bf2_bits(l1);
            }
        }
    }
}

// reduce x_proj split-K partials -> xdbl fp32 + planes
__global__ void reduce_x(const float* __restrict__ part, float* __restrict__ out,
                         __nv_bfloat16* __restrict__ oh, __nv_bfloat16* __restrict__ ol)
{
    int i = blockIdx.x * blockDim.x + threadIdx.x;   // float4 index
    if (i >= ML * 16) return;
    float4 a = reinterpret_cast<const float4*>(part)[i];
    #pragma unroll
    for (int z = 1; z < XKS; z++) {
        float4 b = reinterpret_cast<const float4*>(part + (size_t)z * ML * 64)[i];
        a.x += b.x; a.y += b.y; a.z += b.z; a.w += b.w;
    }
    reinterpret_cast<float4*>(out)[i] = a;
    __nv_bfloat162 h0 = __floats2bfloat162_rn(a.x, a.y);
    __nv_bfloat162 h1 = __floats2bfloat162_rn(a.z, a.w);
    __nv_bfloat162 l0 = __floats2bfloat162_rn(a.x - __bfloat162float(h0.x),
                                              a.y - __bfloat162float(h0.y));
    __nv_bfloat162 l1 = __floats2bfloat162_rn(a.z - __bfloat162float(h1.x),
                                              a.w - __bfloat162float(h1.y));
    reinterpret_cast<uint2*>(oh)[i] = make_uint2(bf2_bits(h0), bf2_bits(h1));
    reinterpret_cast<uint2*>(ol)[i] = make_uint2(bf2_bits(l0), bf2_bits(l1));
}

// ---------------- causal depthwise conv1d + bias + SiLU (+ planes) ----------------
__global__ void conv_silu_kernel(const float* __restrict__ xz,
                                 const float* __restrict__ cw,
                                 const float* __restrict__ cb,
                                 float* __restrict__ xc,
                                 __nv_bfloat16* __restrict__ xch,
                                 __nv_bfloat16* __restrict__ xcl)
{
    int idx = blockIdx.x * blockDim.x + threadIdx.x;
    if (idx >= ML * D_INNER) return;
    int d = idx & (D_INNER - 1);
    int bl = idx >> 10;
    int l = bl & (L_ - 1);
    int b = bl >> 9;

    float w0 = __ldg(&cw[d * 4 + 0]);
    float w1 = __ldg(&cw[d * 4 + 1]);
    float w2 = __ldg(&cw[d * 4 + 2]);
    float w3 = __ldg(&cw[d * 4 + 3]);
    float acc = __ldg(&cb[d]);

    const size_t rowstride = 2 * D_INNER;
    size_t base = ((size_t)b * L_) * rowstride + d;
    if (l >= 3) acc = fmaf(w0, xz[base + (size_t)(l - 3) * rowstride], acc);
    if (l >= 2) acc = fmaf(w1, xz[base + (size_t)(l - 2) * rowstride], acc);
    if (l >= 1) acc = fmaf(w2, xz[base + (size_t)(l - 1) * rowstride], acc);
    acc = fmaf(w3, xz[base + (size_t)l * rowstride], acc);

    float r = act_silu(acc);
    xc[idx] = r;
    __nv_bfloat16 hh = __float2bfloat16(r);
    xch[idx] = hh;
    xcl[idx] = __float2bfloat16(r - __bfloat162float(hh));
}

// ---------------- selective scan (emits y as bf16 hi/lo planes) ----------------
__global__ __launch_bounds__(64) void scan_kernel(
    const float* __restrict__ dt, const float* __restrict__ xc,
    const float* __restrict__ xdbl, const float* __restrict__ xz,
    const float* __restrict__ A_log, const float* __restrict__ Dm,
    __nv_bfloat16* __restrict__ yh, __nv_bfloat16* __restrict__ yl)
{
    const int tid = threadIdx.x;
    const int d = blockIdx.x * 64 + tid;
    const int b = blockIdx.y;

    __shared__ float sBC[2][8][32];

    float Av[D_STATE];
    #pragma unroll
    for (int s = 0; s < D_STATE; s++) Av[s] = -__expf(__ldg(&A_log[d * D_STATE + s]));
    const float Av0 = Av[0];
    int fastl = 1;
    #pragma unroll
    for (int s = 1; s < D_STATE; s++) {
        float tgt = (s + 1) * Av0;
        fastl &= (fabsf(Av[s] - tgt) <= 1e-4f * fabsf(tgt)) ? 1 : 0;
    }
    const int fast = __syncthreads_and(fastl);

    float h[D_STATE];
    #pragma unroll
    for (int s = 0; s < D_STATE; s++) h[s] = 0.f;
    const float Dd = __ldg(&Dm[d]);
    const size_t rowb = (size_t)b * L_;

    float cdt[8], cxc[8], cz[8], ndt[8], nxc[8], nz[8];

    {
        int r = tid >> 3, q = tid & 7;
        float4 v = *reinterpret_cast<const float4*>(&xdbl[(rowb + r) * 64 + 32 + q * 4]);
        *reinterpret_cast<float4*>(&sBC[0][r][q * 4]) = v;
    }
    #pragma unroll
    for (int i = 0; i < 8; i++) {
        size_t row = rowb + i;
        cdt[i] = __ldg(&dt[row * D_INNER + d]);
        cxc[i] = __ldg(&xc[row * D_INNER + d]);
        cz[i]  = __ldg(&xz[row * 2 * D_INNER + D_INNER + d]);
    }
    __syncthreads();

    for (int w = 0; w < L_ / 8; w++) {
        const int slot = w & 1;
        if (w + 1 < L_ / 8) {
            int r = tid >> 3, q = tid & 7;
            float4 v = *reinterpret_cast<const float4*>(
                &xdbl[(rowb + (w + 1) * 8 + r) * 64 + 32 + q * 4]);
            *reinterpret_cast<float4*>(&sBC[slot ^ 1][r][q * 4]) = v;
            #pragma unroll
            for (int i = 0; i < 8; i++) {
                size_t row = rowb + (w + 1) * 8 + i;
                ndt[i] = __ldg(&dt[row * D_INNER + d]);
                nxc[i] = __ldg(&xc[row * D_INNER + d]);
                nz[i]  = __ldg(&xz[row * 2 * D_INNER + D_INNER + d]);
            }
        }

        #pragma unroll
        for (int i = 0; i < 8; i++) {
            const float dtv = cdt[i], xv = cxc[i], zv = cz[i];
            const float p = dtv * xv;
            const float* bc = sBC[slot][i];
            float acc0 = 0.f, acc1 = 0.f;
            if (fast) {
                const float q1 = __expf(dtv * Av0);
                const float q2 = q1 * q1, q3 = q2 * q1, q4 = q2 * q2;
                const float q5 = q4 * q1, q6 = q4 * q2, q7 = q4 * q3, q8 = q4 * q4;
                const float dA[16] = {q1, q2, q3, q4, q5, q6, q7, q8,
                                      q8*q1, q8*q2, q8*q3, q8*q4, q8*q5, q8*q6, q8*q7, q8*q8};
                #pragma unroll
                for (int s = 0; s < D_STATE; s++) {
                    float hs = fmaf(dA[s], h[s], p * bc[s]);
                    h[s] = hs;
                    if (s & 1) acc1 = fmaf(hs, bc[16 + s], acc1);
                    else       acc0 = fmaf(hs, bc[16 + s], acc0);
                }
            } else {
                #pragma unroll
                for (int s = 0; s < D_STATE; s++) {
                    float hs = fmaf(__expf(dtv * Av[s]), h[s], p * bc[s]);
                    h[s] = hs;
                    if (s & 1) acc1 = fmaf(hs, bc[16 + s], acc1);
                    else       acc0 = fmaf(hs, bc[16 + s], acc0);
                }
            }
            const size_t row = rowb + w * 8 + i;
            float yv = fmaf(xv, Dd, acc0 + acc1) * act_silu(zv);
            __nv_bfloat16 hh = __float2bfloat16(yv);
            yh[row * D_INNER + d] = hh;
            yl[row * D_INNER + d] = __float2bfloat16(yv - __bfloat162float(hh));
        }

        #pragma unroll
        for (int i = 0; i < 8; i++) { cdt[i] = ndt[i]; cxc[i] = nxc[i]; cz[i] = nz[i]; }
        __syncthreads();
    }
}

// ---------------- mean over L (2-stage) ----------------
__global__ void mean_part_kernel(const float* __restrict__ h, float* __restrict__ part)
{
    int b = blockIdx.x, lc = blockIdx.y, d = threadIdx.x;
    float acc = 0.f;
    #pragma unroll 8
    for (int l = lc * 64; l < lc * 64 + 64; l++)
        acc += h[((size_t)b * L_ + l) * D_MODEL + d];
    part[(b * 8 + lc) * D_MODEL + d] = acc;
}
__global__ void mean_fin_kernel(const float* __restrict__ part, float* __restrict__ hm)
{
    int i = blockIdx.x * blockDim.x + threadIdx.x;
    if (i >= B_ * D_MODEL) return;
    int b = i / D_MODEL, d = i % D_MODEL;
    float acc = 0.f;
    #pragma unroll
    for (int c = 0; c < 8; c++) acc += part[(b * 8 + c) * D_MODEL + d];
    hm[i] = acc * (1.f / L_);
}

// ---------------- classifier head ----------------
__global__ void cls_kernel(const float* __restrict__ hm,
                           const float* __restrict__ w1, const float* __restrict__ b1,
                           const float* __restrict__ w2, const float* __restrict__ b2,
                           float* __restrict__ out)
{
    int b = blockIdx.x;
    int j = threadIdx.x;
    __shared__ float sh[64];
    float acc = __ldg(&b1[j]);
    const float* hv = hm + b * D_MODEL;
    const float* wv = w1 + j * D_MODEL;
    for (int k = 0; k < D_MODEL; k += 4) {
        float4 hh = *reinterpret_cast<const float4*>(&hv[k]);
        float4 ww = *reinterpret_cast<const float4*>(&wv[k]);
        acc = fmaf(hh.x, ww.x, acc);
        acc = fmaf(hh.y, ww.y, acc);
        acc = fmaf(hh.z, ww.z, acc);
        acc = fmaf(hh.w, ww.w, acc);
    }
    acc = fmaxf(acc, 0.f);
    sh[j] = acc * __ldg(&w2[j]);
    __syncthreads();
    if (j == 0) {
        float s = __ldg(&b2[0]);
        #pragma unroll
        for (int t = 0; t < 64; t++) s += sh[t];
        out[b] = s;
    }
}

// ---------------- launch ----------------
extern "C" void kernel_launch(void* const* d_in, const int* in_sizes, int n_in,
                              void* d_out, int out_size)
{
    const float* x          = (const float*)d_in[0];
    const float* proj_in_w  = (const float*)d_in[1];
    const float* proj_in_b  = (const float*)d_in[2];
    const float* in_proj_w  = (const float*)d_in[3];
    const float* conv_w     = (const float*)d_in[4];
    const float* conv_b     = (const float*)d_in[5];
    const float* x_proj_w   = (const float*)d_in[6];
    const float* dt_proj_w  = (const float*)d_in[7];
    const float* dt_proj_b  = (const float*)d_in[8];
    const float* A_log      = (const float*)d_in[9];
    const float* Dm         = (const float*)d_in[10];
    const float* out_proj_w = (const float*)d_in[11];
    const float* cls_w1     = (const float*)d_in[12];
    const float* cls_b1     = (const float*)d_in[13];
    const float* cls_w2     = (const float*)d_in[14];
    const float* cls_b2     = (const float*)d_in[15];

    void* p;
    cudaGetSymbolAddress(&p, g_ha);    float* ha    = (float*)p;
    cudaGetSymbolAddress(&p, g_xz);    float* xz    = (float*)p;
    cudaGetSymbolAddress(&p, g_xc);    float* xc    = (float*)p;
    cudaGetSymbolAddress(&p, g_xdbl);  float* xdbl  = (float*)p;
    cudaGetSymbolAddress(&p, g_xpart); float* xpart = (float*)p;
    cudaGetSymbolAddress(&p, g_dt);    float* dtb   = (float*)p;
    cudaGetSymbolAddress(&p, g_hpart); float* hpart = (float*)p;
    cudaGetSymbolAddress(&p, g_hm);    float* hm    = (float*)p;

    __nv_bfloat16 *xh, *xl, *piwh, *piwl, *inwh, *inwl, *outwh, *outwl;
    __nv_bfloat16 *xpwh, *xpwl, *dtwh, *dtwl, *hh, *hl, *xch, *xcl, *xdblh, *xdbll, *yh, *yl;
    cudaGetSymbolAddress(&p, g_xh);    xh    = (__nv_bfloat16*)p;
    cudaGetSymbolAddress(&p, g_xl);    xl    = (__nv_bfloat16*)p;
    cudaGetSymbolAddress(&p, g_piwh);  piwh  = (__nv_bfloat16*)p;
    cudaGetSymbolAddress(&p, g_piwl);  piwl  = (__nv_bfloat16*)p;
    cudaGetSymbolAddress(&p, g_inwh);  inwh  = (__nv_bfloat16*)p;
    cudaGetSymbolAddress(&p, g_inwl);  inwl  = (__nv_bfloat16*)p;
    cudaGetSymbolAddress(&p, g_outwh); outwh = (__nv_bfloat16*)p;
    cudaGetSymbolAddress(&p, g_outwl); outwl = (__nv_bfloat16*)p;
    cudaGetSymbolAddress(&p, g_xpwh);  xpwh  = (__nv_bfloat16*)p;
    cudaGetSymbolAddress(&p, g_xpwl);  xpwl  = (__nv_bfloat16*)p;
    cudaGetSymbolAddress(&p, g_dtwh);  dtwh  = (__nv_bfloat16*)p;
    cudaGetSymbolAddress(&p, g_dtwl);  dtwl  = (__nv_bfloat16*)p;
    cudaGetSymbolAddress(&p, g_hh);    hh    = (__nv_bfloat16*)p;
    cudaGetSymbolAddress(&p, g_hl);    hl    = (__nv_bfloat16*)p;
    cudaGetSymbolAddress(&p, g_xch);   xch   = (__nv_bfloat16*)p;
    cudaGetSymbolAddress(&p, g_xcl);   xcl   = (__nv_bfloat16*)p;
    cudaGetSymbolAddress(&p, g_xdblh); xdblh = (__nv_bfloat16*)p;
    cudaGetSymbolAddress(&p, g_xdbll); xdbll = (__nv_bfloat16*)p;
    cudaGetSymbolAddress(&p, g_yh);    yh    = (__nv_bfloat16*)p;
    cudaGetSymbolAddress(&p, g_yl);    yl    = (__nv_bfloat16*)p;

    cudaFuncSetAttribute(gemm_mma, cudaFuncAttributeMaxDynamicSharedMemorySize, MMA_SMEM_BYTES);

    // L1: cvt x + proj_in_w
    {
        int n0 = ML * D_IN / 4, n1 = D_MODEL * D_IN / 4;
        cvt_split2<<<(n0 + n1 + 255) / 256, 256>>>(x, xh, xl, n0, proj_in_w, piwh, piwl, n1);
    }
    // L2: cvt in_proj_w + out_proj_w
    {
        int n0 = N_LAYERS * 2 * D_INNER * D_MODEL / 4, n1 = N_LAYERS * D_MODEL * D_INNER / 4;
        cvt_split2<<<(n0 + n1 + 255) / 256, 256>>>(in_proj_w, inwh, inwl, n0,
                                                   out_proj_w, outwh, outwl, n1);
    }
    // L3: proj_in -> h planes
    gemm_mma<<<dim3(D_MODEL / 128, ML / 128), 512, MMA_SMEM_BYTES>>>(
        xh, xl, D_IN, piwh, piwl, D_IN, proj_in_b,
        nullptr, hh, hl, D_MODEL, D_MODEL, D_IN, 0, 0);

    for (int l = 0; l < N_LAYERS; l++) {
        const size_t inw_off  = (size_t)l * 2 * D_INNER * D_MODEL;
        const size_t outw_off = (size_t)l * D_MODEL * D_INNER;
        const float* cw    = conv_w     + (size_t)l * D_INNER * D_CONV;
        const float* cb    = conv_b     + (size_t)l * D_INNER;
        const float* dt_b  = dt_proj_b  + (size_t)l * D_INNER;
        const float* Al    = A_log      + (size_t)l * D_INNER * D_STATE;
        const float* Dl    = Dm         + (size_t)l * D_INNER;
        const bool last = (l == N_LAYERS - 1);

        // L4 (layer 0; profiled): xz = h @ in_w^T
        gemm_mma<<<dim3(2 * D_INNER / 128, ML / 128), 512, MMA_SMEM_BYTES>>>(
            hh, hl, D_MODEL, inwh + inw_off, inwl + inw_off, D_MODEL,
            nullptr, xz, nullptr, nullptr, 2 * D_INNER, 2 * D_INNER, D_MODEL, 0, 0);

        if (l == 0) {
            // cvt x_proj_w (contiguous into padded 128-row buffers) and dt_proj_w (strided pad)
            int n0 = 64 * D_INNER / 4;
            cvt_split2<<<(2 * n0 + 255) / 256, 256>>>(
                x_proj_w, xpwh, xpwl, n0,
                x_proj_w + 64 * D_INNER, xpwh + 128 * D_INNER, xpwl + 128 * D_INNER, n0);
            cvt_dtw<<<(N_LAYERS * D_INNER * 8 + 255) / 256, 256>>>(dt_proj_w, dtwh, dtwl);
        }

        // conv + silu -> xc fp32 + planes
        conv_silu_kernel<<<(ML * D_INNER) / 256, 256>>>(xz, cw, cb, xc, xch, xcl);

        // x_proj (split-K=4): partials, then reduce -> xdbl fp32 + planes
        gemm_mma<<<dim3(1, ML / 128, XKS), 512, MMA_SMEM_BYTES>>>(
            xch, xcl, D_INNER,
            xpwh + (size_t)l * 128 * D_INNER, xpwl + (size_t)l * 128 * D_INNER, D_INNER,
            nullptr, xpart, nullptr, nullptr, 64, 64, D_INNER / XKS, 0, (size_t)ML * 64);
        reduce_x<<<(ML * 16 + 255) / 256, 256>>>(xpart, xdbl, xdblh, xdbll);

        // dt = softplus(xdbl @ dtw_pad^T + b)   (K=64, pad cols zero)
        gemm_mma<<<dim3(D_INNER / 128, ML / 128), 512, MMA_SMEM_BYTES>>>(
            xdblh, xdbll, 64,
            dtwh + (size_t)l * D_INNER * 64, dtwl + (size_t)l * D_INNER * 64, 64,
            dt_b, dtb, nullptr, nullptr, D_INNER, D_INNER, 64, 1, 0);

        // selective scan -> y planes
        scan_kernel<<<dim3(D_INNER / 64, B_), 64>>>(dtb, xc, xdbl, xz, Al, Dl, yh, yl);

        // out_proj: mid -> h planes; last -> fp32 for mean
        gemm_mma<<<dim3(D_MODEL / 128, ML / 128), 512, MMA_SMEM_BYTES>>>(
            yh, yl, D_INNER, outwh + outw_off, outwl + outw_off, D_INNER,
            nullptr, last ? ha : nullptr, last ? nullptr : hh, last ? nullptr : hl,
            D_MODEL, D_MODEL, D_INNER, 0, 0);
    }

    mean_part_kernel<<<dim3(B_, 8), D_MODEL>>>(ha, hpart);
    mean_fin_kernel<<<(B_ * D_MODEL + 255) / 256, 256>>>(hpart, hm);
    cls_kernel<<<B_, 64>>>(hm, cls_w1, cls_b1, cls_w2, cls_b2, (float*)d_out);
}